// round 1
// baseline (speedup 1.0000x reference)
#include <cuda_runtime.h>

#define VTH 0.5f
#define TAU 0.2f

// x: [N, 4] float32 (steps innermost, contiguous). out: [N, 4] float32 spikes.
// LIF: u = TAU*u*(1-o) + x_t; spike = u > VTH; o = spike.
__global__ void __launch_bounds__(256) lif_kernel(const float4* __restrict__ x,
                                                  float4* __restrict__ out,
                                                  int n4) {
    int i = blockIdx.x * blockDim.x + threadIdx.x;
    if (i >= n4) return;

    float4 v = x[i];

    // t0: u=0, o=0
    float u = v.x;
    float s0 = (u > VTH) ? 1.0f : 0.0f;
    // t1
    u = TAU * u * (1.0f - s0) + v.y;
    float s1 = (u > VTH) ? 1.0f : 0.0f;
    // t2
    u = TAU * u * (1.0f - s1) + v.z;
    float s2 = (u > VTH) ? 1.0f : 0.0f;
    // t3
    u = TAU * u * (1.0f - s2) + v.w;
    float s3 = (u > VTH) ? 1.0f : 0.0f;

    float4 r;
    r.x = s0; r.y = s1; r.z = s2; r.w = s3;
    out[i] = r;
}

extern "C" void kernel_launch(void* const* d_in, const int* in_sizes, int n_in,
                              void* d_out, int out_size) {
    const float4* x = (const float4*)d_in[0];
    float4* out = (float4*)d_out;
    int n4 = out_size / 4;  // number of neurons (each has 4 contiguous steps)

    int threads = 256;
    int blocks = (n4 + threads - 1) / threads;
    lif_kernel<<<blocks, threads>>>(x, out, n4);
}

// round 2
// speedup vs baseline: 1.0300x; 1.0300x over previous
#include <cuda_runtime.h>

#define VTH 0.5f
#define TAU 0.2f

__device__ __forceinline__ float4 lif4(float4 v) {
    float u = v.x;
    float s0 = (u > VTH) ? 1.0f : 0.0f;
    u = TAU * u * (1.0f - s0) + v.y;
    float s1 = (u > VTH) ? 1.0f : 0.0f;
    u = TAU * u * (1.0f - s1) + v.z;
    float s2 = (u > VTH) ? 1.0f : 0.0f;
    u = TAU * u * (1.0f - s2) + v.w;
    float s3 = (u > VTH) ? 1.0f : 0.0f;
    return make_float4(s0, s1, s2, s3);
}

// x: [N, 4] float32 (steps innermost). Each thread handles 2 float4 neurons,
// both loads issued back-to-back (MLP=2) with streaming cache hints.
__global__ void __launch_bounds__(256) lif_kernel2(const float4* __restrict__ x,
                                                   float4* __restrict__ out,
                                                   int n4) {
    int i0 = blockIdx.x * (blockDim.x * 2) + threadIdx.x;
    int i1 = i0 + blockDim.x;

    if (i1 < n4) {
        // Common case: both in range. Issue both loads before any compute.
        float4 v0 = __ldcs(&x[i0]);
        float4 v1 = __ldcs(&x[i1]);
        float4 r0 = lif4(v0);
        float4 r1 = lif4(v1);
        __stcs(&out[i0], r0);
        __stcs(&out[i1], r1);
    } else if (i0 < n4) {
        float4 v0 = __ldcs(&x[i0]);
        __stcs(&out[i0], lif4(v0));
    }
}

extern "C" void kernel_launch(void* const* d_in, const int* in_sizes, int n_in,
                              void* d_out, int out_size) {
    const float4* x = (const float4*)d_in[0];
    float4* out = (float4*)d_out;
    int n4 = out_size / 4;  // number of neurons (4 contiguous steps each)

    int threads = 256;
    int per_block = threads * 2;
    int blocks = (n4 + per_block - 1) / per_block;
    lif_kernel2<<<blocks, threads>>>(x, out, n4);
}